// round 1
// baseline (speedup 1.0000x reference)
#include <cuda_runtime.h>

// LinearAttention: per (b,l) site (16384 sites):
//   qf = elu(q)+1, kf = elu(k)+1           [32,64]
//   A  = qf @ kf^T                          [32,32]  (contract E=64)
//   y[h] = 1/(rowsum_h'(A[h,:]) + eps)               (== qf . sum_h kf)
//   x[h,d] = y[h] * L^-0.5 * sum_h' A[h,h'] v[h',d]  [32,64]
// This is the 2x-cheaper re-association of (Q @ (K^T V)).

#define HH 32
#define EE 64
#define DD 64
#define ROWPAD 68       // floats per padded row (272B: 16B-aligned, conflict-free)
#define APAD 36         // A row pad (144B, 16B-aligned)
#define EPSV 1e-6f
#define RSQRT_L 0.022097086912079608f   // 2048^-0.5

typedef unsigned long long u64;

__device__ __forceinline__ u64 f2fma(u64 a, u64 b, u64 c) {
    u64 d;
    asm("fma.rn.f32x2 %0, %1, %2, %3;" : "=l"(d) : "l"(a), "l"(b), "l"(c));
    return d;
}
__device__ __forceinline__ u64 f2mul(u64 a, u64 b) {
    u64 d;
    asm("mul.rn.f32x2 %0, %1, %2;" : "=l"(d) : "l"(a), "l"(b));
    return d;
}
__device__ __forceinline__ u64 pk2(float lo, float hi) {
    u64 r;
    asm("mov.b64 %0, {%1, %2};" : "=l"(r) : "f"(lo), "f"(hi));
    return r;
}
__device__ __forceinline__ float2 unpk(u64 v) {
    float2 r;
    asm("mov.b64 {%0, %1}, %2;" : "=f"(r.x), "=f"(r.y) : "l"(v));
    return r;
}
__device__ __forceinline__ float elu1(float x) {
    return x > 0.0f ? x + 1.0f : expf(x);
}

__global__ void __launch_bounds__(128, 6) linattn_kernel(
    const float* __restrict__ Q, const float* __restrict__ K,
    const float* __restrict__ V, float* __restrict__ O)
{
    __shared__ float sQ[HH * ROWPAD];
    __shared__ float sK[HH * ROWPAD];
    __shared__ float sV[HH * ROWPAD];
    __shared__ float sA[HH * APAD];
    __shared__ float sY[HH];

    const int tid  = threadIdx.x;
    const size_t site = blockIdx.x;
    const float4* q4 = (const float4*)(Q + site * (HH * EE));
    const float4* k4 = (const float4*)(K + site * (HH * EE));
    const float4* v4 = (const float4*)(V + site * (HH * DD));

    // ---- Load + elu+1 (q,k), raw copy (v). 512 float4s, 128 threads. ----
    #pragma unroll
    for (int it = 0; it < 4; ++it) {
        int f  = tid + it * 128;      // float4 index 0..511
        int h  = f >> 4;
        int e4 = (f & 15) << 2;
        float4 a = q4[f];
        a.x = elu1(a.x); a.y = elu1(a.y); a.z = elu1(a.z); a.w = elu1(a.w);
        *(float4*)&sQ[h * ROWPAD + e4] = a;
        float4 b = k4[f];
        b.x = elu1(b.x); b.y = elu1(b.y); b.z = elu1(b.z); b.w = elu1(b.w);
        *(float4*)&sK[h * ROWPAD + e4] = b;
        *(float4*)&sV[h * ROWPAD + e4] = v4[f];
    }
    __syncthreads();

    // ---- Stage 1: A[h,h'] = sum_e qf[h,e] kf[h',e]  (packed along e) ----
    // thread tile: 2 h rows x 4 h' cols.  hq = t&7 (h' quad), hp = t>>3 (h pair)
    {
        const int hq = tid & 7;
        const int hp = tid >> 3;
        const float* qr0 = &sQ[(hp * 2) * ROWPAD];
        const float* qr1 = qr0 + ROWPAD;
        const float* kr  = &sK[(hq * 4) * ROWPAD];

        u64 acc[2][4];
        #pragma unroll
        for (int i = 0; i < 2; ++i)
            #pragma unroll
            for (int j = 0; j < 4; ++j) acc[i][j] = 0ULL;

        #pragma unroll
        for (int e0 = 0; e0 < EE; e0 += 4) {
            ulonglong2 p0 = *(const ulonglong2*)(qr0 + e0);  // (q.x,q.y),(q.z,q.w)
            ulonglong2 p1 = *(const ulonglong2*)(qr1 + e0);
            #pragma unroll
            for (int j = 0; j < 4; ++j) {
                ulonglong2 kk = *(const ulonglong2*)(kr + j * ROWPAD + e0);
                acc[0][j] = f2fma(p0.x, kk.x, acc[0][j]);
                acc[0][j] = f2fma(p0.y, kk.y, acc[0][j]);
                acc[1][j] = f2fma(p1.x, kk.x, acc[1][j]);
                acc[1][j] = f2fma(p1.y, kk.y, acc[1][j]);
            }
        }
        // horizontal reduce pairs, store A as float4 per row
        #pragma unroll
        for (int i = 0; i < 2; ++i) {
            float4 r;
            float2 t0 = unpk(acc[i][0]); r.x = t0.x + t0.y;
            float2 t1 = unpk(acc[i][1]); r.y = t1.x + t1.y;
            float2 t2 = unpk(acc[i][2]); r.z = t2.x + t2.y;
            float2 t3 = unpk(acc[i][3]); r.w = t3.x + t3.y;
            *(float4*)&sA[(hp * 2 + i) * APAD + hq * 4] = r;
        }
    }
    __syncthreads();

    // ---- y[h] = L^-0.5 / (rowsum(A) + eps) ----
    if (tid < HH) {
        const float* ar = &sA[tid * APAD];
        float s = 0.0f;
        #pragma unroll
        for (int j = 0; j < HH; ++j) s += ar[j];
        sY[tid] = RSQRT_L / (s + EPSV);
    }
    __syncthreads();

    // ---- Stage 2: x[h,d] = y[h] * sum_h' A[h,h'] v[h',d] (packed along d) ----
    // thread tile: 2 h rows x 8 d (d = dg*4 + c*32 + j)
    {
        const int dg = tid & 7;
        const int hp = tid >> 3;
        const float* a0 = &sA[(hp * 2) * APAD];
        const float* a1 = a0 + APAD;

        u64 acc[2][2][2];   // [h_i][c][pair]
        #pragma unroll
        for (int i = 0; i < 2; ++i)
            #pragma unroll
            for (int c = 0; c < 2; ++c) { acc[i][c][0] = 0ULL; acc[i][c][1] = 0ULL; }

        #pragma unroll
        for (int hh = 0; hh < HH; ++hh) {
            float av0 = a0[hh];
            float av1 = a1[hh];
            u64 pa0 = pk2(av0, av0);
            u64 pa1 = pk2(av1, av1);
            ulonglong2 v0 = *(const ulonglong2*)&sV[hh * ROWPAD + dg * 4];
            ulonglong2 v1 = *(const ulonglong2*)&sV[hh * ROWPAD + dg * 4 + 32];
            acc[0][0][0] = f2fma(pa0, v0.x, acc[0][0][0]);
            acc[0][0][1] = f2fma(pa0, v0.y, acc[0][0][1]);
            acc[0][1][0] = f2fma(pa0, v1.x, acc[0][1][0]);
            acc[0][1][1] = f2fma(pa0, v1.y, acc[0][1][1]);
            acc[1][0][0] = f2fma(pa1, v0.x, acc[1][0][0]);
            acc[1][0][1] = f2fma(pa1, v0.y, acc[1][0][1]);
            acc[1][1][0] = f2fma(pa1, v1.x, acc[1][1][0]);
            acc[1][1][1] = f2fma(pa1, v1.y, acc[1][1][1]);
        }

        float y0 = sY[hp * 2];
        float y1 = sY[hp * 2 + 1];
        u64 py0 = pk2(y0, y0);
        u64 py1 = pk2(y1, y1);

        float* ob = O + site * (HH * DD) + (hp * 2) * DD + dg * 4;
        ulonglong2 w;
        w.x = f2mul(acc[0][0][0], py0); w.y = f2mul(acc[0][0][1], py0);
        *(ulonglong2*)(ob) = w;
        w.x = f2mul(acc[0][1][0], py0); w.y = f2mul(acc[0][1][1], py0);
        *(ulonglong2*)(ob + 32) = w;
        w.x = f2mul(acc[1][0][0], py1); w.y = f2mul(acc[1][0][1], py1);
        *(ulonglong2*)(ob + DD) = w;
        w.x = f2mul(acc[1][1][0], py1); w.y = f2mul(acc[1][1][1], py1);
        *(ulonglong2*)(ob + DD + 32) = w;
    }
}

extern "C" void kernel_launch(void* const* d_in, const int* in_sizes, int n_in,
                              void* d_out, int out_size) {
    const float* Q = (const float*)d_in[0];
    const float* K = (const float*)d_in[1];
    const float* V = (const float*)d_in[2];
    float* O = (float*)d_out;
    int nsites = in_sizes[0] / (HH * EE);   // B*L = 16384
    linattn_kernel<<<nsites, 128>>>(Q, K, V, O);
}

// round 2
// speedup vs baseline: 2.0082x; 2.0082x over previous
#include <cuda_runtime.h>

// LinearAttention: per (b,l) site (16384 sites):
//   qf = elu(q)+1, kf = elu(k)+1           [32,64]
//   A  = qf @ kf^T                          [32,32]  (contract E=64)
//   y[h] = L^-0.5 / (rowsum_h'(A[h,:]) + eps)
//   x[h,d] = y[h] * sum_h' A[h,h'] v[h',d]  [32,64]
//
// R2: conflict-free row remap in stage 1 (rows {hp,hp+16} x {hq+8j}),
//     vectorized A loads in stage 2, MUFU-based elu, occupancy 7.

#define HH 32
#define EE 64
#define DD 64
#define RP 68           // padded row stride (272B): hq*272 % 128 = hq*16 -> conflict-free
#define APAD 36         // A row stride (144B)
#define EPSV 1e-6f
#define RSQRT_L 0.022097086912079608f   // 2048^-0.5

typedef unsigned long long u64;

__device__ __forceinline__ u64 f2fma(u64 a, u64 b, u64 c) {
    u64 d;
    asm("fma.rn.f32x2 %0, %1, %2, %3;" : "=l"(d) : "l"(a), "l"(b), "l"(c));
    return d;
}
__device__ __forceinline__ u64 f2mul(u64 a, u64 b) {
    u64 d;
    asm("mul.rn.f32x2 %0, %1, %2;" : "=l"(d) : "l"(a), "l"(b));
    return d;
}
__device__ __forceinline__ u64 pk2(float lo, float hi) {
    u64 r;
    asm("mov.b64 %0, {%1, %2};" : "=l"(r) : "f"(lo), "f"(hi));
    return r;
}
__device__ __forceinline__ float2 unpk(u64 v) {
    float2 r;
    asm("mov.b64 {%0, %1}, %2;" : "=f"(r.x), "=f"(r.y) : "l"(v));
    return r;
}
__device__ __forceinline__ float elu1(float x) {
    // x>0: x+1 ; else exp(x) = 2^(x*log2e)  (1 MUFU)
    float r;
    asm("ex2.approx.ftz.f32 %0, %1;" : "=f"(r) : "f"(x * 1.4426950408889634f));
    return x > 0.0f ? x + 1.0f : r;
}

__global__ void __launch_bounds__(128, 7) linattn_kernel(
    const float* __restrict__ Q, const float* __restrict__ K,
    const float* __restrict__ V, float* __restrict__ O)
{
    __shared__ float sQ[HH * RP];
    __shared__ float sK[HH * RP];
    __shared__ float sV[HH * RP];
    __shared__ float sA[HH * APAD];
    __shared__ float sY[HH];

    const int tid  = threadIdx.x;
    const size_t site = blockIdx.x;
    const float4* q4 = (const float4*)(Q + site * (HH * EE));
    const float4* k4 = (const float4*)(K + site * (HH * EE));
    const float4* v4 = (const float4*)(V + site * (HH * DD));

    // ---- Load + elu+1 (q,k), raw copy (v). 512 float4s, 128 threads. ----
    #pragma unroll
    for (int it = 0; it < 4; ++it) {
        int f  = tid + it * 128;      // float4 index 0..511
        int h  = f >> 4;
        int e4 = (f & 15) << 2;
        float4 a = q4[f];
        a.x = elu1(a.x); a.y = elu1(a.y); a.z = elu1(a.z); a.w = elu1(a.w);
        *(float4*)&sQ[h * RP + e4] = a;
        float4 b = k4[f];
        b.x = elu1(b.x); b.y = elu1(b.y); b.z = elu1(b.z); b.w = elu1(b.w);
        *(float4*)&sK[h * RP + e4] = b;
        *(float4*)&sV[h * RP + e4] = v4[f];
    }
    __syncthreads();

    // ---- Stage 1: A[h,h'] = sum_e qf[h,e] kf[h',e]  (packed along e) ----
    // Conflict-free remap: q-rows {hp, hp+16}, k-rows {hq+8j}, j=0..3.
    {
        const int hq = tid & 7;       // 0..7
        const int hp = tid >> 3;      // 0..15
        const float* qr0 = &sQ[hp * RP];
        const float* qr1 = &sQ[(hp + 16) * RP];
        const float* kr  = &sK[hq * RP];   // + j*8*RP for row hq+8j

        u64 acc[2][4];
        #pragma unroll
        for (int i = 0; i < 2; ++i)
            #pragma unroll
            for (int j = 0; j < 4; ++j) acc[i][j] = 0ULL;

        #pragma unroll
        for (int e0 = 0; e0 < EE; e0 += 4) {
            ulonglong2 p0 = *(const ulonglong2*)(qr0 + e0);
            ulonglong2 p1 = *(const ulonglong2*)(qr1 + e0);
            #pragma unroll
            for (int j = 0; j < 4; ++j) {
                ulonglong2 kk = *(const ulonglong2*)(kr + j * (8 * RP) + e0);
                acc[0][j] = f2fma(p0.x, kk.x, acc[0][j]);
                acc[0][j] = f2fma(p0.y, kk.y, acc[0][j]);
                acc[1][j] = f2fma(p1.x, kk.x, acc[1][j]);
                acc[1][j] = f2fma(p1.y, kk.y, acc[1][j]);
            }
        }
        // horizontal reduce pairs, scattered scalar stores (verified N=1)
        #pragma unroll
        for (int i = 0; i < 2; ++i) {
            #pragma unroll
            for (int j = 0; j < 4; ++j) {
                float2 t = unpk(acc[i][j]);
                sA[(hp + 16 * i) * APAD + (hq + 8 * j)] = t.x + t.y;
            }
        }
    }
    __syncthreads();

    // ---- y[h] = L^-0.5 / (rowsum(A) + eps) ----
    if (tid < HH) {
        const float4* ar = (const float4*)&sA[tid * APAD];
        float s = 0.0f;
        #pragma unroll
        for (int j = 0; j < HH / 4; ++j) {
            float4 t = ar[j];
            s += (t.x + t.y) + (t.z + t.w);
        }
        sY[tid] = RSQRT_L / (s + EPSV);
    }
    __syncthreads();

    // ---- Stage 2: x[h,d] = y[h] * sum_h' A[h,h'] v[h',d] (packed along d) ----
    // thread tile: rows {2hp, 2hp+1} x 8 d (d = dg*4 + {0..3} and +32)
    {
        const int dg = tid & 7;
        const int hp = tid >> 3;
        const float* a0 = &sA[(hp * 2) * APAD];
        const float* a1 = a0 + APAD;

        u64 acc[2][2][2];   // [row][d-half][pair]
        #pragma unroll
        for (int i = 0; i < 2; ++i)
            #pragma unroll
            for (int c = 0; c < 2; ++c) { acc[i][c][0] = 0ULL; acc[i][c][1] = 0ULL; }

        #pragma unroll
        for (int hh0 = 0; hh0 < HH; hh0 += 4) {
            float4 av0 = *(const float4*)(a0 + hh0);
            float4 av1 = *(const float4*)(a1 + hh0);
            #pragma unroll
            for (int u = 0; u < 4; ++u) {
                int hh = hh0 + u;
                float s0 = (u == 0) ? av0.x : (u == 1) ? av0.y : (u == 2) ? av0.z : av0.w;
                float s1 = (u == 0) ? av1.x : (u == 1) ? av1.y : (u == 2) ? av1.z : av1.w;
                u64 pa0 = pk2(s0, s0);
                u64 pa1 = pk2(s1, s1);
                ulonglong2 v0 = *(const ulonglong2*)&sV[hh * RP + dg * 4];
                ulonglong2 v1 = *(const ulonglong2*)&sV[hh * RP + dg * 4 + 32];
                acc[0][0][0] = f2fma(pa0, v0.x, acc[0][0][0]);
                acc[0][0][1] = f2fma(pa0, v0.y, acc[0][0][1]);
                acc[0][1][0] = f2fma(pa0, v1.x, acc[0][1][0]);
                acc[0][1][1] = f2fma(pa0, v1.y, acc[0][1][1]);
                acc[1][0][0] = f2fma(pa1, v0.x, acc[1][0][0]);
                acc[1][0][1] = f2fma(pa1, v0.y, acc[1][0][1]);
                acc[1][1][0] = f2fma(pa1, v1.x, acc[1][1][0]);
                acc[1][1][1] = f2fma(pa1, v1.y, acc[1][1][1]);
            }
        }

        float y0 = sY[hp * 2];
        float y1 = sY[hp * 2 + 1];
        u64 py0 = pk2(y0, y0);
        u64 py1 = pk2(y1, y1);

        float* ob = O + site * (HH * DD) + (hp * 2) * DD + dg * 4;
        ulonglong2 w;
        w.x = f2mul(acc[0][0][0], py0); w.y = f2mul(acc[0][0][1], py0);
        *(ulonglong2*)(ob) = w;
        w.x = f2mul(acc[0][1][0], py0); w.y = f2mul(acc[0][1][1], py0);
        *(ulonglong2*)(ob + 32) = w;
        w.x = f2mul(acc[1][0][0], py1); w.y = f2mul(acc[1][0][1], py1);
        *(ulonglong2*)(ob + DD) = w;
        w.x = f2mul(acc[1][1][0], py1); w.y = f2mul(acc[1][1][1], py1);
        *(ulonglong2*)(ob + DD + 32) = w;
    }
}

extern "C" void kernel_launch(void* const* d_in, const int* in_sizes, int n_in,
                              void* d_out, int out_size) {
    const float* Q = (const float*)d_in[0];
    const float* K = (const float*)d_in[1];
    const float* V = (const float*)d_in[2];
    float* O = (float*)d_out;
    int nsites = in_sizes[0] / (HH * EE);   // B*L = 16384
    linattn_kernel<<<nsites, 128>>>(Q, K, V, O);
}

// round 3
// speedup vs baseline: 2.4246x; 1.2074x over previous
#include <cuda_runtime.h>

// LinearAttention per (b,l) site (16384 sites):
//   qf=elu(q)+1, kf=elu(k)+1 [32,64]; A = qf@kf^T [32,32];
//   y[h] = L^-0.5/(rowsum(A)+eps); x = diag(y) A V [32,64].
// R3: 64-thread CTAs, warp split-K (stage1) / split-H' (stage2),
//     32-output register tiles -> smem request bytes 360KB -> ~200KB/site.

#define HH 32
#define EE 64
#define DD 64
#define RP 68       // q/k/v row pitch (272B): bank-group = row mod 8
#define APAD 36     // A row pitch (144B): bank-group = (row + chunk) mod 8
#define PPAD 33     // partial row pitch (f32: 132B / u64: 264B)
#define EPSV 1e-6f
#define RSQRT_L 0.022097086912079608f   // 2048^-0.5

typedef unsigned long long u64;

__device__ __forceinline__ u64 f2fma(u64 a, u64 b, u64 c) {
    u64 d;
    asm("fma.rn.f32x2 %0, %1, %2, %3;" : "=l"(d) : "l"(a), "l"(b), "l"(c));
    return d;
}
__device__ __forceinline__ u64 f2mul(u64 a, u64 b) {
    u64 d;
    asm("mul.rn.f32x2 %0, %1, %2;" : "=l"(d) : "l"(a), "l"(b));
    return d;
}
__device__ __forceinline__ u64 pk2(float lo, float hi) {
    u64 r;
    asm("mov.b64 %0, {%1, %2};" : "=l"(r) : "f"(lo), "f"(hi));
    return r;
}
__device__ __forceinline__ float2 unpk(u64 v) {
    float2 r;
    asm("mov.b64 {%0, %1}, %2;" : "=f"(r.x), "=f"(r.y) : "l"(v));
    return r;
}
__device__ __forceinline__ float foldp(u64 v) {
    float2 t = unpk(v);
    return t.x + t.y;
}
__device__ __forceinline__ float elu1(float x) {
    float r;
    asm("ex2.approx.ftz.f32 %0, %1;" : "=f"(r) : "f"(x * 1.4426950408889634f));
    return x > 0.0f ? x + 1.0f : r;
}

__global__ void __launch_bounds__(64, 6) linattn_kernel(
    const float* __restrict__ Q, const float* __restrict__ K,
    const float* __restrict__ V, float* __restrict__ O)
{
    __shared__ __align__(16) float sQ[HH * RP];   // reused as stage-2 partial buffer
    __shared__ __align__(16) float sK[HH * RP];
    __shared__ __align__(16) float sV[HH * RP];
    __shared__ __align__(16) float sA[HH * APAD];
    __shared__ __align__(16) float sP1[HH * PPAD];

    const int tid = threadIdx.x;
    const int w   = tid >> 5;       // warp 0/1
    const int ln  = tid & 31;
    const size_t site = blockIdx.x;

    const float4* q4 = (const float4*)(Q + site * (HH * EE));
    const float4* k4 = (const float4*)(K + site * (HH * EE));
    const float4* v4 = (const float4*)(V + site * (HH * DD));

    // ---- Load + elu+1 (q,k), raw copy (v). 512 float4s, 64 threads. ----
    #pragma unroll
    for (int it = 0; it < 8; ++it) {
        int f  = tid + it * 64;       // 0..511
        int h  = f >> 4;
        int e4 = (f & 15) << 2;
        float4 a = q4[f];
        a.x = elu1(a.x); a.y = elu1(a.y); a.z = elu1(a.z); a.w = elu1(a.w);
        *(float4*)&sQ[h * RP + e4] = a;
        float4 b = k4[f];
        b.x = elu1(b.x); b.y = elu1(b.y); b.z = elu1(b.z); b.w = elu1(b.w);
        *(float4*)&sK[h * RP + e4] = b;
        *(float4*)&sV[h * RP + e4] = v4[f];
    }
    __syncthreads();

    // ================= Stage 1: A = qf @ kf^T, split-K by warp =========
    // warp w covers e in [32w, 32w+32). Lane tile: rows {rg+8i}, cols {cg+4j}.
    {
        const int rg = ln & 7;
        const int cg = ln >> 3;
        const int eb = 32 * w;

        u64 acc[4][8];
        #pragma unroll
        for (int i = 0; i < 4; ++i)
            #pragma unroll
            for (int j = 0; j < 8; ++j) acc[i][j] = 0ULL;

        #pragma unroll
        for (int c = 0; c < 8; ++c) {
            int e0 = eb + 4 * c;
            ulonglong2 qv[4];
            #pragma unroll
            for (int i = 0; i < 4; ++i)
                qv[i] = *(const ulonglong2*)&sQ[(rg + 8 * i) * RP + e0];
            #pragma unroll
            for (int j = 0; j < 8; ++j) {
                ulonglong2 kv = *(const ulonglong2*)&sK[(cg + 4 * j) * RP + e0];
                #pragma unroll
                for (int i = 0; i < 4; ++i) {
                    acc[i][j] = f2fma(qv[i].x, kv.x, acc[i][j]);
                    acc[i][j] = f2fma(qv[i].y, kv.y, acc[i][j]);
                }
            }
        }

        if (w == 1) {
            // fold e-pairs, publish f32 partials
            #pragma unroll
            for (int i = 0; i < 4; ++i)
                #pragma unroll
                for (int j = 0; j < 8; ++j)
                    sP1[ln * PPAD + (i * 8 + j)] = foldp(acc[i][j]);
        }
        __syncthreads();   // sync1: partials visible

        if (w == 0) {
            #pragma unroll
            for (int i = 0; i < 4; ++i)
                #pragma unroll
                for (int j = 0; j < 8; ++j) {
                    float a = foldp(acc[i][j]) + sP1[ln * PPAD + (i * 8 + j)];
                    sA[(rg + 8 * i) * APAD + (cg + 4 * j)] = a;
                }
        }
        __syncthreads();   // sync2: A complete; sQ now dead
    }

    // ---- warp0 computes y[ln] (held in register; shfl'd at epilogue) ----
    float yv = 0.0f;
    if (w == 0) {
        const float4* ar = (const float4*)&sA[ln * APAD];
        float s = 0.0f;
        #pragma unroll
        for (int j = 0; j < HH / 4; ++j) {
            float4 t = ar[j];
            s += (t.x + t.y) + (t.z + t.w);
        }
        yv = RSQRT_L / (s + EPSV);
    }

    // ================= Stage 2: X = A @ V, split-H' by warp ============
    // warp w covers h' in [16w, 16w+16). Lane tile: rows {rg2+4i} (8 rows),
    // d in {4dg..4dg+3} and {4dg+32..4dg+35}.
    {
        const int rg2 = ln & 3;
        const int dg  = ln >> 2;
        const int hb  = 16 * w;
        u64* sP2 = (u64*)sQ;   // overlay: stage-2 partial buffer (u64, pitch PPAD)

        u64 xa[8][4];
        #pragma unroll
        for (int i = 0; i < 8; ++i)
            #pragma unroll
            for (int k = 0; k < 4; ++k) xa[i][k] = 0ULL;

        #pragma unroll
        for (int hc = 0; hc < 4; ++hc) {
            float4 av[8];
            #pragma unroll
            for (int i = 0; i < 8; ++i)
                av[i] = *(const float4*)&sA[(rg2 + 4 * i) * APAD + hb + 4 * hc];
            #pragma unroll
            for (int u = 0; u < 4; ++u) {
                int hh = hb + 4 * hc + u;
                ulonglong2 v0 = *(const ulonglong2*)&sV[hh * RP + 4 * dg];
                ulonglong2 v1 = *(const ulonglong2*)&sV[hh * RP + 4 * dg + 32];
                #pragma unroll
                for (int i = 0; i < 8; ++i) {
                    float s  = (u == 0) ? av[i].x : (u == 1) ? av[i].y
                             : (u == 2) ? av[i].z : av[i].w;
                    u64 ps = pk2(s, s);
                    xa[i][0] = f2fma(ps, v0.x, xa[i][0]);
                    xa[i][1] = f2fma(ps, v0.y, xa[i][1]);
                    xa[i][2] = f2fma(ps, v1.x, xa[i][2]);
                    xa[i][3] = f2fma(ps, v1.y, xa[i][3]);
                }
            }
        }

        if (w == 1) {
            #pragma unroll
            for (int i = 0; i < 8; ++i)
                #pragma unroll
                for (int k = 0; k < 4; ++k)
                    sP2[ln * PPAD + (i * 4 + k)] = xa[i][k];
        }
        __syncthreads();   // sync3: stage-2 partials visible

        if (w == 0) {
            float* ob = O + site * (size_t)(HH * DD);
            #pragma unroll
            for (int i = 0; i < 8; ++i) {
                int row = rg2 + 4 * i;
                float yi = __shfl_sync(0xffffffffu, yv, row);
                u64 py = pk2(yi, yi);
                ulonglong2 w0, w1;
                w0.x = f2mul(f2fma(pk2(1.f,1.f), sP2[ln * PPAD + (i*4+0)], xa[i][0]), py);
                w0.y = f2mul(f2fma(pk2(1.f,1.f), sP2[ln * PPAD + (i*4+1)], xa[i][1]), py);
                w1.x = f2mul(f2fma(pk2(1.f,1.f), sP2[ln * PPAD + (i*4+2)], xa[i][2]), py);
                w1.y = f2mul(f2fma(pk2(1.f,1.f), sP2[ln * PPAD + (i*4+3)], xa[i][3]), py);
                *(ulonglong2*)(ob + row * DD + 4 * dg)      = w0;
                *(ulonglong2*)(ob + row * DD + 4 * dg + 32) = w1;
            }
        }
    }
}

extern "C" void kernel_launch(void* const* d_in, const int* in_sizes, int n_in,
                              void* d_out, int out_size) {
    const float* Q = (const float*)d_in[0];
    const float* K = (const float*)d_in[1];
    const float* V = (const float*)d_in[2];
    float* O = (float*)d_out;
    int nsites = in_sizes[0] / (HH * EE);   // B*L = 16384
    linattn_kernel<<<nsites, 64>>>(Q, K, V, O);
}